// round 4
// baseline (speedup 1.0000x reference)
#include <cuda_runtime.h>
#include <cuda_bf16.h>
#include <cstdint>

typedef unsigned long long ull;
typedef unsigned int u32;

// Problem constants (fixed shapes per reference)
#define NN    100000
#define EE    1600000
#define CINn  64
#define COUTn 128
#define SCAN_B 512

// ---------------- scratch (static device globals; no runtime alloc) ----------------
__device__ float g_agg0[(size_t)NN * CINn];
__device__ float g_agg1[(size_t)NN * COUTn];
__device__ float g_h0[(size_t)NN * COUTn];
__device__ float g_y[(size_t)NN * COUTn];
__device__ float g_h1[(size_t)NN * COUTn];
__device__ float g_r[(size_t)NN * COUTn];
__device__ float g_stats[4 * COUTn];
__device__ float g_bnp[4 * COUTn];
// CSR scratch
__device__ int g_deg[NN];
__device__ int g_lscan[NN];
__device__ int g_part[256];
__device__ int g_rowptr[NN + 1];
__device__ int g_cursor[NN];
__device__ int g_eidx[EE];
// bf16 hi/lo weight buffers: wlin, wr0, wn0 (128x64 each), wr1, wn1 (128x128)
#define WB_WLIN 0
#define WB_WR0  16384
#define WB_WN0  32768
#define WB_WR1  49152
#define WB_WN1  81920
__device__ __nv_bfloat16 g_wb[114688];

// pack two fp32 -> bf16x2 (a -> low half, b -> high half)
__device__ __forceinline__ u32 bpack(float a, float b) {
    u32 r;
    asm("cvt.rn.bf16x2.f32 %0, %1, %2;" : "=r"(r) : "f"(b), "f"(a));
    return r;
}

// HMMA m16n8k16 bf16 -> fp32 accumulate (baseline PTX, no arch-feature suffix)
#define MMA_BF16(c, a, b)                                                     \
    asm volatile("mma.sync.aligned.m16n8k16.row.col.f32.bf16.bf16.f32 "       \
                 "{%0,%1,%2,%3}, {%4,%5,%6,%7}, {%8,%9}, {%0,%1,%2,%3};"      \
                 : "+f"((c)[0]), "+f"((c)[1]), "+f"((c)[2]), "+f"((c)[3])     \
                 : "r"((a)[0]), "r"((a)[1]), "r"((a)[2]), "r"((a)[3]),        \
                   "r"((b)[0]), "r"((b)[1]))

// =============================================================================
// Weight prep: fp32 -> bf16 hi (out[0:n]) + bf16 lo (out[n:2n])
// =============================================================================
__global__ void wprep_kernel(const float* __restrict__ w, __nv_bfloat16* __restrict__ out,
                             int n) {
    const int i = blockIdx.x * blockDim.x + threadIdx.x;
    if (i >= n) return;
    const float v = w[i];
    const __nv_bfloat16 h = __float2bfloat16(v);
    out[i]     = h;
    out[n + i] = __float2bfloat16(v - __bfloat162float(h));
}

// =============================================================================
// HMMA GEMM: C[row,0:128] = sum over passes of Apass @ Wpass^T + bias.
// 3-term bf16 split per pass (Ah@Wh + Ah@Wl + Al@Wh), fp32 accumulate in regs.
// CTA tile 128x128, 8 warps (2x4), warp tile 64x32 via m16n8k16 fragments.
// SMEM row-major with stride K+8 (bank-conflict-free fragment loads).
// Optionally fuses per-column BN stats (sum, sumsq) into the epilogue.
// =============================================================================
__global__ __launch_bounds__(256, 1) void gemm_mma_kernel(
    const float* __restrict__ A0, const __nv_bfloat16* __restrict__ W0,
    const float* __restrict__ A1, const __nv_bfloat16* __restrict__ W1,
    const float* __restrict__ bias, float* __restrict__ C,
    float* __restrict__ stats, int Nn, int K, int npass) {

    extern __shared__ char dsm[];
    float* ssum = (float*)dsm;          // 128 floats
    float* ssq  = ssum + 128;           // 128 floats (stats region = 1024 B)
    const int stride = K + 8;
    __nv_bfloat16* pAh = (__nv_bfloat16*)(dsm + 1024);
    __nv_bfloat16* pAl = pAh + 128 * stride;
    __nv_bfloat16* pWh = pAl + 128 * stride;
    __nv_bfloat16* pWl = pWh + 128 * stride;

    const int tid = threadIdx.x;
    const int wid = tid >> 5, lane = tid & 31;
    const int g = lane >> 2, t = lane & 3;
    const int warp_m = wid >> 2;       // 0..1 -> 64-row halves
    const int warp_n = wid & 3;        // 0..3 -> 32-col quarters
    const int mrow = warp_m * 64;
    const int ncol = warp_n * 32;
    const int row0 = blockIdx.x * 128;

    if (stats && tid < 128) { ssum[tid] = 0.f; ssq[tid] = 0.f; }

    float acc[4][4][4];
#pragma unroll
    for (int a = 0; a < 4; a++)
#pragma unroll
        for (int b = 0; b < 4; b++)
#pragma unroll
            for (int c = 0; c < 4; c++) acc[a][b][c] = 0.f;

    const int kq = K >> 2;          // float4s / uint2s per row
    const int quads = 128 * kq;
    const int ksteps = K >> 4;

    for (int pass = 0; pass < npass; pass++) {
        if (pass) __syncthreads();   // previous compute done before restaging
        const float* Ap = pass ? A1 : A0;
        const __nv_bfloat16* Whi = pass ? W1 : W0;
        const __nv_bfloat16* Wlo = Whi + 128 * K;

        // stage A tile: fp32 -> bf16 hi/lo into padded row-major smem
        for (int idx = tid; idx < quads; idx += 256) {
            const int row = idx / kq;
            const int k0 = (idx - row * kq) << 2;
            const int gr = row0 + row;
            float4 v = make_float4(0.f, 0.f, 0.f, 0.f);
            if (gr < Nn) v = *(const float4*)(Ap + (size_t)gr * K + k0);
            const float hx = __bfloat162float(__float2bfloat16(v.x));
            const float hy = __bfloat162float(__float2bfloat16(v.y));
            const float hz = __bfloat162float(__float2bfloat16(v.z));
            const float hw = __bfloat162float(__float2bfloat16(v.w));
            const int so = row * stride + k0;
            *(uint2*)(pAh + so) = make_uint2(bpack(v.x, v.y), bpack(v.z, v.w));
            *(uint2*)(pAl + so) = make_uint2(bpack(v.x - hx, v.y - hy),
                                             bpack(v.z - hz, v.w - hw));
        }
        // stage W tiles (pre-split bf16 hi/lo)
        for (int idx = tid; idx < quads; idx += 256) {
            const int n = idx / kq;
            const int k0 = (idx - n * kq) << 2;
            const size_t off = (size_t)n * K + k0;
            const int so = n * stride + k0;
            *(uint2*)(pWh + so) = *(const uint2*)(Whi + off);
            *(uint2*)(pWl + so) = *(const uint2*)(Wlo + off);
        }
        __syncthreads();

        for (int ks = 0; ks < ksteps; ks++) {
            const int k0 = ks * 16;
            u32 ah[4][4], al[4][4], bh[4][2], bl[4][2];
#pragma unroll
            for (int mt = 0; mt < 4; mt++) {
                const int base = (mrow + mt * 16 + g) * stride + k0 + t * 2;
                ah[mt][0] = *(const u32*)(pAh + base);
                ah[mt][1] = *(const u32*)(pAh + base + 8 * stride);
                ah[mt][2] = *(const u32*)(pAh + base + 8);
                ah[mt][3] = *(const u32*)(pAh + base + 8 * stride + 8);
                al[mt][0] = *(const u32*)(pAl + base);
                al[mt][1] = *(const u32*)(pAl + base + 8 * stride);
                al[mt][2] = *(const u32*)(pAl + base + 8);
                al[mt][3] = *(const u32*)(pAl + base + 8 * stride + 8);
            }
#pragma unroll
            for (int nt = 0; nt < 4; nt++) {
                const int base = (ncol + nt * 8 + g) * stride + k0 + t * 2;
                bh[nt][0] = *(const u32*)(pWh + base);
                bh[nt][1] = *(const u32*)(pWh + base + 8);
                bl[nt][0] = *(const u32*)(pWl + base);
                bl[nt][1] = *(const u32*)(pWl + base + 8);
            }
#pragma unroll
            for (int mt = 0; mt < 4; mt++)
#pragma unroll
                for (int nt = 0; nt < 4; nt++) {
                    MMA_BF16(acc[mt][nt], ah[mt], bh[nt]);
                    MMA_BF16(acc[mt][nt], ah[mt], bl[nt]);
                    MMA_BF16(acc[mt][nt], al[mt], bh[nt]);
                }
        }
    }

    // ---------------- epilogue: bias, store, fused BN stats ----------------
    float bcol[4][2];
#pragma unroll
    for (int nt = 0; nt < 4; nt++) {
        const int c = ncol + nt * 8 + t * 2;
        bcol[nt][0] = __ldg(bias + c);
        bcol[nt][1] = __ldg(bias + c + 1);
    }
    float psum[4][2] = {}, psq[4][2] = {};
#pragma unroll
    for (int mt = 0; mt < 4; mt++) {
        const int r0 = row0 + mrow + mt * 16 + g;
        const int r1 = r0 + 8;
#pragma unroll
        for (int nt = 0; nt < 4; nt++) {
            const int c = ncol + nt * 8 + t * 2;
            if (r0 < Nn) {
                float2 o;
                o.x = acc[mt][nt][0] + bcol[nt][0];
                o.y = acc[mt][nt][1] + bcol[nt][1];
                *(float2*)(C + (size_t)r0 * 128 + c) = o;
                psum[nt][0] += o.x; psum[nt][1] += o.y;
                psq[nt][0] += o.x * o.x; psq[nt][1] += o.y * o.y;
            }
            if (r1 < Nn) {
                float2 o;
                o.x = acc[mt][nt][2] + bcol[nt][0];
                o.y = acc[mt][nt][3] + bcol[nt][1];
                *(float2*)(C + (size_t)r1 * 128 + c) = o;
                psum[nt][0] += o.x; psum[nt][1] += o.y;
                psq[nt][0] += o.x * o.x; psq[nt][1] += o.y * o.y;
            }
        }
    }
    if (stats) {
#pragma unroll
        for (int nt = 0; nt < 4; nt++) {
            const int c = ncol + nt * 8 + t * 2;
            atomicAdd(&ssum[c], psum[nt][0]);
            atomicAdd(&ssum[c + 1], psum[nt][1]);
            atomicAdd(&ssq[c], psq[nt][0]);
            atomicAdd(&ssq[c + 1], psq[nt][1]);
        }
        __syncthreads();
        if (tid < 128) {
            atomicAdd(&stats[tid], ssum[tid]);
            atomicAdd(&stats[128 + tid], ssq[tid]);
        }
    }
}

// =============================================================================
// CSR build: histogram -> scan -> fill
// =============================================================================
__global__ void hist_kernel(const int* __restrict__ dst, int* __restrict__ deg, int E) {
    const int e = blockIdx.x * blockDim.x + threadIdx.x;
    if (e < E) atomicAdd(&deg[dst[e]], 1);
}

__global__ void scan1_kernel(const int* __restrict__ deg, int* __restrict__ lscan,
                             int* __restrict__ part, int N) {
    __shared__ int sh[SCAN_B];
    const int i = blockIdx.x * SCAN_B + threadIdx.x;
    const int v = (i < N) ? deg[i] : 0;
    sh[threadIdx.x] = v;
    __syncthreads();
#pragma unroll
    for (int off = 1; off < SCAN_B; off <<= 1) {
        int tv = (threadIdx.x >= off) ? sh[threadIdx.x - off] : 0;
        __syncthreads();
        sh[threadIdx.x] += tv;
        __syncthreads();
    }
    if (i < N) lscan[i] = sh[threadIdx.x] - v;
    if (threadIdx.x == SCAN_B - 1) part[blockIdx.x] = sh[threadIdx.x];
}

__global__ void scan2_kernel(int* __restrict__ part, int nb) {
    __shared__ int sh[256];
    const int v = (threadIdx.x < nb) ? part[threadIdx.x] : 0;
    sh[threadIdx.x] = v;
    __syncthreads();
#pragma unroll
    for (int off = 1; off < 256; off <<= 1) {
        int tv = (threadIdx.x >= off) ? sh[threadIdx.x - off] : 0;
        __syncthreads();
        sh[threadIdx.x] += tv;
        __syncthreads();
    }
    if (threadIdx.x < nb) part[threadIdx.x] = sh[threadIdx.x] - v;
}

__global__ void scan3_kernel(const int* __restrict__ lscan, const int* __restrict__ part,
                             int* __restrict__ rowptr, int* __restrict__ cursor,
                             int N, int E) {
    const int i = blockIdx.x * blockDim.x + threadIdx.x;
    if (i < N) {
        const int r = lscan[i] + part[i / SCAN_B];
        rowptr[i] = r;
        cursor[i] = r;
    }
    if (i == 0) rowptr[N] = E;
}

__global__ void fill_kernel(const int* __restrict__ src, const int* __restrict__ dst,
                            int* __restrict__ cursor, int* __restrict__ eidx, int E) {
    const int e = blockIdx.x * blockDim.x + threadIdx.x;
    if (e < E) {
        const int pos = atomicAdd(&cursor[dst[e]], 1);
        eidx[pos] = src[e];
    }
}

// =============================================================================
// Gather aggregation (CSR): agg[n] = sum_{in-edges} feat[src]
// =============================================================================
template <int C4>
__global__ void gather_kernel(const int* __restrict__ rowptr, const int* __restrict__ eidx,
                              const float4* __restrict__ feat, float4* __restrict__ agg,
                              int N) {
    constexpr int NPB = 256 / C4;
    const int g = threadIdx.x / C4;
    const int c = threadIdx.x % C4;
    const int node = blockIdx.x * NPB + g;
    if (node >= N) return;
    const int beg = rowptr[node];
    const int end = rowptr[node + 1];
    float4 acc = make_float4(0.f, 0.f, 0.f, 0.f);
    int e = beg;
    for (; e + 1 < end; e += 2) {
        const int s0 = eidx[e];
        const int s1 = eidx[e + 1];
        const float4 v0 = feat[(size_t)s0 * C4 + c];
        const float4 v1 = feat[(size_t)s1 * C4 + c];
        acc.x += v0.x; acc.y += v0.y; acc.z += v0.z; acc.w += v0.w;
        acc.x += v1.x; acc.y += v1.y; acc.z += v1.z; acc.w += v1.w;
    }
    if (e < end) {
        const int s = eidx[e];
        const float4 v = feat[(size_t)s * C4 + c];
        acc.x += v.x; acc.y += v.y; acc.z += v.z; acc.w += v.w;
    }
    agg[(size_t)node * C4 + c] = acc;
}

// ---------------- BN finalize ----------------
__global__ void finalize_kernel(const float* __restrict__ stats,
                                const float* __restrict__ gamma,
                                const float* __restrict__ beta,
                                float* __restrict__ bnp, float invN) {
    const int c = threadIdx.x;
    const float mu   = stats[c] * invN;
    const float var  = stats[128 + c] * invN - mu * mu;
    const float rstd = rsqrtf(var + 1e-5f);
    const float sc   = rstd * gamma[c];
    bnp[c]       = sc;
    bnp[128 + c] = beta[c] - mu * sc;
}

// ---------------- y = relu(h*scale + shift) ----------------
__global__ void bnrelu_kernel(const float4* __restrict__ h, const float* __restrict__ bnp,
                              float4* __restrict__ y, int total4) {
    const int i = blockIdx.x * blockDim.x + threadIdx.x;
    if (i >= total4) return;
    const int c = (i & 31) * 4;
    const float4 v = h[i];
    float4 o;
    o.x = fmaxf(fmaf(v.x, bnp[c + 0], bnp[128 + c + 0]), 0.f);
    o.y = fmaxf(fmaf(v.y, bnp[c + 1], bnp[128 + c + 1]), 0.f);
    o.z = fmaxf(fmaf(v.z, bnp[c + 2], bnp[128 + c + 2]), 0.f);
    o.w = fmaxf(fmaf(v.w, bnp[c + 3], bnp[128 + c + 3]), 0.f);
    y[i] = o;
}

// ---------------- out = relu(h1*scale + shift + r) ----------------
__global__ void final_kernel(const float4* __restrict__ h1, const float* __restrict__ bnp,
                             const float4* __restrict__ r, float4* __restrict__ out,
                             int total4) {
    const int i = blockIdx.x * blockDim.x + threadIdx.x;
    if (i >= total4) return;
    const int c = (i & 31) * 4;
    const float4 v = h1[i];
    const float4 rv = r[i];
    float4 o;
    o.x = fmaxf(fmaf(v.x, bnp[c + 0], bnp[128 + c + 0]) + rv.x, 0.f);
    o.y = fmaxf(fmaf(v.y, bnp[c + 1], bnp[128 + c + 1]) + rv.y, 0.f);
    o.z = fmaxf(fmaf(v.z, bnp[c + 2], bnp[128 + c + 2]) + rv.z, 0.f);
    o.w = fmaxf(fmaf(v.w, bnp[c + 3], bnp[128 + c + 3]) + rv.w, 0.f);
    out[i] = o;
}

// ---------------- launch ----------------
extern "C" void kernel_launch(void* const* d_in, const int* in_sizes, int n_in,
                              void* d_out, int out_size) {
    const float* x    = (const float*)d_in[0];
    const int*   ei   = (const int*)d_in[1];
    const float* Wr0  = (const float*)d_in[2];
    const float* Wn0  = (const float*)d_in[3];
    const float* b0   = (const float*)d_in[4];
    const float* g0   = (const float*)d_in[5];
    const float* be0  = (const float*)d_in[6];
    const float* Wr1  = (const float*)d_in[7];
    const float* Wn1  = (const float*)d_in[8];
    const float* b1   = (const float*)d_in[9];
    const float* g1   = (const float*)d_in[10];
    const float* be1  = (const float*)d_in[11];
    const float* Wlin = (const float*)d_in[12];
    const float* blin = (const float*)d_in[13];
    float* out = (float*)d_out;

    const int N = in_sizes[0] / CINn;
    const int E = in_sizes[1] / 2;
    const int* src = ei;
    const int* dst = ei + E;

    float *agg0, *agg1, *h0, *y, *h1, *r, *stats, *bnp;
    int *deg, *lscan, *part, *rowptr, *cursor, *eidx;
    __nv_bfloat16* wb;
    cudaGetSymbolAddress((void**)&agg0,   g_agg0);
    cudaGetSymbolAddress((void**)&agg1,   g_agg1);
    cudaGetSymbolAddress((void**)&h0,     g_h0);
    cudaGetSymbolAddress((void**)&y,      g_y);
    cudaGetSymbolAddress((void**)&h1,     g_h1);
    cudaGetSymbolAddress((void**)&r,      g_r);
    cudaGetSymbolAddress((void**)&stats,  g_stats);
    cudaGetSymbolAddress((void**)&bnp,    g_bnp);
    cudaGetSymbolAddress((void**)&deg,    g_deg);
    cudaGetSymbolAddress((void**)&lscan,  g_lscan);
    cudaGetSymbolAddress((void**)&part,   g_part);
    cudaGetSymbolAddress((void**)&rowptr, g_rowptr);
    cudaGetSymbolAddress((void**)&cursor, g_cursor);
    cudaGetSymbolAddress((void**)&eidx,   g_eidx);
    cudaGetSymbolAddress((void**)&wb,     g_wb);

    // dynamic smem: 1024 stats + 4 bf16 tiles of 128 x (K+8)
    const int smem64  = 1024 + 4 * 128 * (64 + 8) * 2;    // 74752
    const int smem128 = 1024 + 4 * 128 * (128 + 8) * 2;   // 140288
    cudaFuncSetAttribute(gemm_mma_kernel, cudaFuncAttributeMaxDynamicSharedMemorySize,
                         smem128);

    cudaMemsetAsync(deg,   0, (size_t)N * sizeof(int));
    cudaMemsetAsync(stats, 0, 4 * COUTn * sizeof(float));

    // ---- weight prep (fp32 -> bf16 hi/lo) ----
    wprep_kernel<<<32, 256>>>(Wlin, wb + WB_WLIN, 128 * 64);
    wprep_kernel<<<32, 256>>>(Wr0,  wb + WB_WR0,  128 * 64);
    wprep_kernel<<<32, 256>>>(Wn0,  wb + WB_WN0,  128 * 64);
    wprep_kernel<<<64, 256>>>(Wr1,  wb + WB_WR1,  128 * 128);
    wprep_kernel<<<64, 256>>>(Wn1,  wb + WB_WN1,  128 * 128);

    const int nb = (N + SCAN_B - 1) / SCAN_B;

    // ---- CSR build ----
    hist_kernel<<<(E + 255) / 256, 256>>>(dst, deg, E);
    scan1_kernel<<<nb, SCAN_B>>>(deg, lscan, part, N);
    scan2_kernel<<<1, 256>>>(part, nb);
    scan3_kernel<<<(N + 255) / 256, 256>>>(lscan, part, rowptr, cursor, N, E);
    fill_kernel<<<(E + 255) / 256, 256>>>(src, dst, cursor, eidx, E);

    const int tiles = (N + 127) / 128;
    const int T4 = N * 32;

    // ---- Layer 0 ----
    gather_kernel<16><<<(N + 15) / 16, 256>>>(rowptr, eidx, (const float4*)x,
                                              (float4*)agg0, N);
    // r = x @ Wlin^T + blin
    gemm_mma_kernel<<<tiles, 256, smem64>>>(x, wb + WB_WLIN, nullptr, nullptr,
                                            blin, r, nullptr, N, 64, 1);
    // h0 = x @ Wr0^T + agg0 @ Wn0^T + b0 (+ fused BN stats)
    gemm_mma_kernel<<<tiles, 256, smem64>>>(x, wb + WB_WR0, agg0, wb + WB_WN0,
                                            b0, h0, stats, N, 64, 2);
    finalize_kernel<<<1, 128>>>(stats, g0, be0, bnp, 1.0f / (float)N);
    bnrelu_kernel<<<(T4 + 255) / 256, 256>>>((const float4*)h0, bnp, (float4*)y, T4);

    // ---- Layer 1 ----
    gather_kernel<32><<<(N + 7) / 8, 256>>>(rowptr, eidx, (const float4*)y,
                                            (float4*)agg1, N);
    // h1 = y @ Wr1^T + agg1 @ Wn1^T + b1 (+ fused BN stats)
    gemm_mma_kernel<<<tiles, 256, smem128>>>(y, wb + WB_WR1, agg1, wb + WB_WN1,
                                             b1, h1, stats + 2 * COUTn, N, 128, 2);
    finalize_kernel<<<1, 128>>>(stats + 2 * COUTn, g1, be1, bnp + 2 * COUTn, 1.0f / (float)N);
    final_kernel<<<(T4 + 255) / 256, 256>>>((const float4*)h1, bnp + 2 * COUTn,
                                            (const float4*)r, (float4*)out, T4);
}

// round 5
// speedup vs baseline: 1.3830x; 1.3830x over previous
#include <cuda_runtime.h>
#include <cstdint>

typedef unsigned long long ull;

// Problem constants (fixed shapes per reference)
#define NN    100000
#define EE    1600000
#define CINn  64
#define COUTn 128
#define SCAN_B 512

// ---------------- scratch (static device globals; no runtime alloc) ----------------
__device__ float g_agg0[(size_t)NN * CINn];
__device__ float g_agg1[(size_t)NN * COUTn];
__device__ float g_h0[(size_t)NN * COUTn];
__device__ float g_y[(size_t)NN * COUTn];
__device__ float g_h1[(size_t)NN * COUTn];
__device__ float g_r[(size_t)NN * COUTn];
__device__ float g_stats[4 * COUTn];
__device__ float g_bnp[4 * COUTn];
// CSR scratch
__device__ int g_deg[NN];
__device__ int g_lscan[NN];
__device__ int g_part[256];
__device__ int g_rowptr[NN + 1];
__device__ int g_cursor[NN];
__device__ int g_eidx[EE];

// ---------------- packed fp32x2 FMA (sm_103a FFMA2 path) ----------------
#define FMA2(acc, a, w) \
    asm("fma.rn.f32x2 %0, %1, %2, %0;" : "+l"(acc) : "l"(a), "l"(w))

__device__ __forceinline__ ull dup2(float f) {
    ull r;
    asm("mov.b64 %0, {%1, %1};" : "=l"(r) : "f"(f));
    return r;
}

union F2 { ull u; float2 f; };
union W4 { float4 v; ull u[2]; };

// =============================================================================
// CSR build: histogram -> scan -> fill
// =============================================================================
__global__ void hist_kernel(const int* __restrict__ dst, int* __restrict__ deg, int E) {
    const int e = blockIdx.x * blockDim.x + threadIdx.x;
    if (e < E) atomicAdd(&deg[dst[e]], 1);
}

__global__ void scan1_kernel(const int* __restrict__ deg, int* __restrict__ lscan,
                             int* __restrict__ part, int N) {
    __shared__ int sh[SCAN_B];
    const int i = blockIdx.x * SCAN_B + threadIdx.x;
    const int v = (i < N) ? deg[i] : 0;
    sh[threadIdx.x] = v;
    __syncthreads();
#pragma unroll
    for (int off = 1; off < SCAN_B; off <<= 1) {
        int t = (threadIdx.x >= off) ? sh[threadIdx.x - off] : 0;
        __syncthreads();
        sh[threadIdx.x] += t;
        __syncthreads();
    }
    if (i < N) lscan[i] = sh[threadIdx.x] - v;
    if (threadIdx.x == SCAN_B - 1) part[blockIdx.x] = sh[threadIdx.x];
}

__global__ void scan2_kernel(int* __restrict__ part, int nb) {
    __shared__ int sh[256];
    const int v = (threadIdx.x < nb) ? part[threadIdx.x] : 0;
    sh[threadIdx.x] = v;
    __syncthreads();
#pragma unroll
    for (int off = 1; off < 256; off <<= 1) {
        int t = (threadIdx.x >= off) ? sh[threadIdx.x - off] : 0;
        __syncthreads();
        sh[threadIdx.x] += t;
        __syncthreads();
    }
    if (threadIdx.x < nb) part[threadIdx.x] = sh[threadIdx.x] - v;
}

__global__ void scan3_kernel(const int* __restrict__ lscan, const int* __restrict__ part,
                             int* __restrict__ rowptr, int* __restrict__ cursor,
                             int N, int E) {
    const int i = blockIdx.x * blockDim.x + threadIdx.x;
    if (i < N) {
        const int r = lscan[i] + part[i / SCAN_B];
        rowptr[i] = r;
        cursor[i] = r;
    }
    if (i == 0) rowptr[N] = E;
}

__global__ void fill_kernel(const int* __restrict__ src, const int* __restrict__ dst,
                            int* __restrict__ cursor, int* __restrict__ eidx, int E) {
    const int e = blockIdx.x * blockDim.x + threadIdx.x;
    if (e < E) {
        const int pos = atomicAdd(&cursor[dst[e]], 1);
        eidx[pos] = src[e];
    }
}

// =============================================================================
// Gather aggregation (CSR): agg[n] = sum_{in-edges} feat[src], 4-edge unrolled
// =============================================================================
template <int C4>
__global__ void gather_kernel(const int* __restrict__ rowptr, const int* __restrict__ eidx,
                              const float4* __restrict__ feat, float4* __restrict__ agg,
                              int N) {
    constexpr int NPB = 256 / C4;
    const int g = threadIdx.x / C4;
    const int c = threadIdx.x % C4;
    const int node = blockIdx.x * NPB + g;
    if (node >= N) return;
    const int beg = rowptr[node];
    const int end = rowptr[node + 1];
    float4 acc = make_float4(0.f, 0.f, 0.f, 0.f);
    int e = beg;
    for (; e + 3 < end; e += 4) {
        const int s0 = eidx[e];
        const int s1 = eidx[e + 1];
        const int s2 = eidx[e + 2];
        const int s3 = eidx[e + 3];
        const float4 v0 = feat[(size_t)s0 * C4 + c];
        const float4 v1 = feat[(size_t)s1 * C4 + c];
        const float4 v2 = feat[(size_t)s2 * C4 + c];
        const float4 v3 = feat[(size_t)s3 * C4 + c];
        acc.x += v0.x + v1.x + v2.x + v3.x;
        acc.y += v0.y + v1.y + v2.y + v3.y;
        acc.z += v0.z + v1.z + v2.z + v3.z;
        acc.w += v0.w + v1.w + v2.w + v3.w;
    }
    for (; e < end; e++) {
        const int s = eidx[e];
        const float4 v = feat[(size_t)s * C4 + c];
        acc.x += v.x; acc.y += v.y; acc.z += v.z; acc.w += v.w;
    }
    agg[(size_t)node * C4 + c] = acc;
}

// =============================================================================
// Tiled fp32x2 GEMM: C[n,0:128] = A@W1^T (+ B@W2^T) + bias, optional BN stats.
// BM=64, BN=128, BK=16, 256 threads. Inner loop: 4x LDS.128 (A broadcast) +
// 1x LDS.128 (W) + 16x fma.rn.f32x2 per k-step.
// =============================================================================
__global__ __launch_bounds__(256) void gemm_kernel(
    const float* __restrict__ A, const float* __restrict__ W1,
    const float* __restrict__ B, const float* __restrict__ W2,
    const float* __restrict__ bias, float* __restrict__ C,
    float* __restrict__ stats, int Nn, int K) {

    __shared__ alignas(16) ull As2[16 * 66];   // [k][m] dup pairs, stride 66 (16B align)
    __shared__ alignas(16) float Ws[16][128];
    __shared__ float sh_sum[128];
    __shared__ float sh_sq[128];

    const int tid  = threadIdx.x;
    const int row0 = blockIdx.x * 64;
    const int warp = tid >> 5;
    const int lane = tid & 31;
    const int tm   = warp * 8;   // 8 rows per thread
    const int tn   = lane * 4;   // 4 cols per thread

    if (stats && tid < 128) { sh_sum[tid] = 0.f; sh_sq[tid] = 0.f; }

    ull acc2[8][2];
#pragma unroll
    for (int i = 0; i < 8; i++) { acc2[i][0] = 0ull; acc2[i][1] = 0ull; }

    const int nmat = (B != nullptr) ? 2 : 1;
    for (int mat = 0; mat < nmat; mat++) {
        const float* Ap = mat ? B : A;
        const float* Wp = mat ? W2 : W1;
        for (int k0 = 0; k0 < K; k0 += 16) {
            // A tile: 64 rows x 16 k, stored duplicated (a,a)
            {
                const int m  = tid >> 2;
                const int kq = (tid & 3) * 4;
                const int r  = row0 + m;
                float4 v = make_float4(0.f, 0.f, 0.f, 0.f);
                if (r < Nn) v = *(const float4*)(Ap + (size_t)r * K + k0 + kq);
                As2[(kq + 0) * 66 + m] = dup2(v.x);
                As2[(kq + 1) * 66 + m] = dup2(v.y);
                As2[(kq + 2) * 66 + m] = dup2(v.z);
                As2[(kq + 3) * 66 + m] = dup2(v.w);
            }
            // W tile: 128 n x 16 k -> Ws[k][n]
            {
                const int n  = tid >> 1;
                const int kq = (tid & 1) * 8;
                const float* wrow = Wp + (size_t)n * K + k0 + kq;
                float4 v0 = *(const float4*)(wrow);
                float4 v1 = *(const float4*)(wrow + 4);
                Ws[kq + 0][n] = v0.x; Ws[kq + 1][n] = v0.y;
                Ws[kq + 2][n] = v0.z; Ws[kq + 3][n] = v0.w;
                Ws[kq + 4][n] = v1.x; Ws[kq + 5][n] = v1.y;
                Ws[kq + 6][n] = v1.z; Ws[kq + 7][n] = v1.w;
            }
            __syncthreads();
#pragma unroll
            for (int kk = 0; kk < 16; kk++) {
                const ulonglong2* ap = (const ulonglong2*)&As2[kk * 66 + tm];
                const ulonglong2 a01 = ap[0];   // LDS.128 broadcast
                const ulonglong2 a23 = ap[1];
                const ulonglong2 a45 = ap[2];
                const ulonglong2 a67 = ap[3];
                W4 w;
                w.v = *(const float4*)&Ws[kk][tn];   // LDS.128
                FMA2(acc2[0][0], a01.x, w.u[0]); FMA2(acc2[0][1], a01.x, w.u[1]);
                FMA2(acc2[1][0], a01.y, w.u[0]); FMA2(acc2[1][1], a01.y, w.u[1]);
                FMA2(acc2[2][0], a23.x, w.u[0]); FMA2(acc2[2][1], a23.x, w.u[1]);
                FMA2(acc2[3][0], a23.y, w.u[0]); FMA2(acc2[3][1], a23.y, w.u[1]);
                FMA2(acc2[4][0], a45.x, w.u[0]); FMA2(acc2[4][1], a45.x, w.u[1]);
                FMA2(acc2[5][0], a45.y, w.u[0]); FMA2(acc2[5][1], a45.y, w.u[1]);
                FMA2(acc2[6][0], a67.x, w.u[0]); FMA2(acc2[6][1], a67.x, w.u[1]);
                FMA2(acc2[7][0], a67.y, w.u[0]); FMA2(acc2[7][1], a67.y, w.u[1]);
            }
            __syncthreads();
        }
    }

    // ---------------- epilogue: bias, store, fused BN stats ----------------
    const float bb0 = bias[tn], bb1 = bias[tn + 1], bb2 = bias[tn + 2], bb3 = bias[tn + 3];
    float psum[4] = {0.f, 0.f, 0.f, 0.f};
    float psq[4]  = {0.f, 0.f, 0.f, 0.f};
#pragma unroll
    for (int i = 0; i < 8; i++) {
        const int r = row0 + tm + i;
        if (r < Nn) {
            F2 p0, p1;
            p0.u = acc2[i][0];
            p1.u = acc2[i][1];
            float4 o;
            o.x = p0.f.x + bb0; o.y = p0.f.y + bb1;
            o.z = p1.f.x + bb2; o.w = p1.f.y + bb3;
            *(float4*)(C + (size_t)r * 128 + tn) = o;
            psum[0] += o.x; psum[1] += o.y; psum[2] += o.z; psum[3] += o.w;
            psq[0] += o.x * o.x; psq[1] += o.y * o.y;
            psq[2] += o.z * o.z; psq[3] += o.w * o.w;
        }
    }
    if (stats) {
#pragma unroll
        for (int j = 0; j < 4; j++) {
            atomicAdd(&sh_sum[tn + j], psum[j]);
            atomicAdd(&sh_sq[tn + j], psq[j]);
        }
        __syncthreads();
        if (tid < 128) {
            atomicAdd(&stats[tid], sh_sum[tid]);
            atomicAdd(&stats[128 + tid], sh_sq[tid]);
        }
    }
}

// ---------------- BN finalize ----------------
__global__ void finalize_kernel(const float* __restrict__ stats,
                                const float* __restrict__ gamma,
                                const float* __restrict__ beta,
                                float* __restrict__ bnp, float invN) {
    const int c = threadIdx.x;  // 128 threads
    const float mu   = stats[c] * invN;
    const float var  = stats[128 + c] * invN - mu * mu;
    const float rstd = rsqrtf(var + 1e-5f);
    const float sc   = rstd * gamma[c];
    bnp[c]       = sc;
    bnp[128 + c] = beta[c] - mu * sc;
}

// ---------------- y = relu(h*scale + shift) ----------------
__global__ void bnrelu_kernel(const float4* __restrict__ h, const float* __restrict__ bnp,
                              float4* __restrict__ y, int total4) {
    const int i = blockIdx.x * blockDim.x + threadIdx.x;
    if (i >= total4) return;
    const int c = (i & 31) * 4;
    const float4 v = h[i];
    float4 o;
    o.x = fmaxf(fmaf(v.x, bnp[c + 0], bnp[128 + c + 0]), 0.f);
    o.y = fmaxf(fmaf(v.y, bnp[c + 1], bnp[128 + c + 1]), 0.f);
    o.z = fmaxf(fmaf(v.z, bnp[c + 2], bnp[128 + c + 2]), 0.f);
    o.w = fmaxf(fmaf(v.w, bnp[c + 3], bnp[128 + c + 3]), 0.f);
    y[i] = o;
}

// ---------------- out = relu(h1*scale + shift + r) ----------------
__global__ void final_kernel(const float4* __restrict__ h1, const float* __restrict__ bnp,
                             const float4* __restrict__ r, float4* __restrict__ out,
                             int total4) {
    const int i = blockIdx.x * blockDim.x + threadIdx.x;
    if (i >= total4) return;
    const int c = (i & 31) * 4;
    const float4 v = h1[i];
    const float4 rv = r[i];
    float4 o;
    o.x = fmaxf(fmaf(v.x, bnp[c + 0], bnp[128 + c + 0]) + rv.x, 0.f);
    o.y = fmaxf(fmaf(v.y, bnp[c + 1], bnp[128 + c + 1]) + rv.y, 0.f);
    o.z = fmaxf(fmaf(v.z, bnp[c + 2], bnp[128 + c + 2]) + rv.z, 0.f);
    o.w = fmaxf(fmaf(v.w, bnp[c + 3], bnp[128 + c + 3]) + rv.w, 0.f);
    out[i] = o;
}

// ---------------- launch ----------------
extern "C" void kernel_launch(void* const* d_in, const int* in_sizes, int n_in,
                              void* d_out, int out_size) {
    const float* x    = (const float*)d_in[0];
    const int*   ei   = (const int*)d_in[1];
    const float* Wr0  = (const float*)d_in[2];
    const float* Wn0  = (const float*)d_in[3];
    const float* b0   = (const float*)d_in[4];
    const float* g0   = (const float*)d_in[5];
    const float* be0  = (const float*)d_in[6];
    const float* Wr1  = (const float*)d_in[7];
    const float* Wn1  = (const float*)d_in[8];
    const float* b1   = (const float*)d_in[9];
    const float* g1   = (const float*)d_in[10];
    const float* be1  = (const float*)d_in[11];
    const float* Wlin = (const float*)d_in[12];
    const float* blin = (const float*)d_in[13];
    float* out = (float*)d_out;

    const int N = in_sizes[0] / CINn;
    const int E = in_sizes[1] / 2;
    const int* src = ei;
    const int* dst = ei + E;

    float *agg0, *agg1, *h0, *y, *h1, *r, *stats, *bnp;
    int *deg, *lscan, *part, *rowptr, *cursor, *eidx;
    cudaGetSymbolAddress((void**)&agg0,   g_agg0);
    cudaGetSymbolAddress((void**)&agg1,   g_agg1);
    cudaGetSymbolAddress((void**)&h0,     g_h0);
    cudaGetSymbolAddress((void**)&y,      g_y);
    cudaGetSymbolAddress((void**)&h1,     g_h1);
    cudaGetSymbolAddress((void**)&r,      g_r);
    cudaGetSymbolAddress((void**)&stats,  g_stats);
    cudaGetSymbolAddress((void**)&bnp,    g_bnp);
    cudaGetSymbolAddress((void**)&deg,    g_deg);
    cudaGetSymbolAddress((void**)&lscan,  g_lscan);
    cudaGetSymbolAddress((void**)&part,   g_part);
    cudaGetSymbolAddress((void**)&rowptr, g_rowptr);
    cudaGetSymbolAddress((void**)&cursor, g_cursor);
    cudaGetSymbolAddress((void**)&eidx,   g_eidx);

    cudaMemsetAsync(deg,   0, (size_t)N * sizeof(int));
    cudaMemsetAsync(stats, 0, 4 * COUTn * sizeof(float));

    const int nb = (N + SCAN_B - 1) / SCAN_B;

    // ---- CSR build (once; reused by both layers) ----
    hist_kernel<<<(E + 255) / 256, 256>>>(dst, deg, E);
    scan1_kernel<<<nb, SCAN_B>>>(deg, lscan, part, N);
    scan2_kernel<<<1, 256>>>(part, nb);
    scan3_kernel<<<(N + 255) / 256, 256>>>(lscan, part, rowptr, cursor, N, E);
    fill_kernel<<<(E + 255) / 256, 256>>>(src, dst, cursor, eidx, E);

    const int gemmBlocks = (N + 63) / 64;
    const int T4 = N * 32;

    // ---- Layer 0 ----
    gather_kernel<16><<<(N + 15) / 16, 256>>>(rowptr, eidx, (const float4*)x,
                                              (float4*)agg0, N);
    // r = x @ Wlin^T + blin
    gemm_kernel<<<gemmBlocks, 256>>>(x, Wlin, nullptr, nullptr, blin, r, nullptr, N, CINn);
    // h0 = x @ Wr0^T + agg0 @ Wn0^T + b0 (+ fused BN stats)
    gemm_kernel<<<gemmBlocks, 256>>>(x, Wr0, agg0, Wn0, b0, h0, stats, N, CINn);
    finalize_kernel<<<1, 128>>>(stats, g0, be0, bnp, 1.0f / (float)N);
    bnrelu_kernel<<<(T4 + 255) / 256, 256>>>((const float4*)h0, bnp, (float4*)y, T4);

    // ---- Layer 1 ----
    gather_kernel<32><<<(N + 7) / 8, 256>>>(rowptr, eidx, (const float4*)y,
                                            (float4*)agg1, N);
    // h1 = y @ Wr1^T + agg1 @ Wn1^T + b1 (+ fused BN stats)
    gemm_kernel<<<gemmBlocks, 256>>>(y, Wr1, agg1, Wn1, b1, h1, stats + 2 * COUTn, N, COUTn);
    finalize_kernel<<<1, 128>>>(stats + 2 * COUTn, g1, be1, bnp + 2 * COUTn, 1.0f / (float)N);
    final_kernel<<<(T4 + 255) / 256, 256>>>((const float4*)h1, bnp + 2 * COUTn,
                                            (const float4*)r, (float4*)out, T4);
}